// round 6
// baseline (speedup 1.0000x reference)
#include <cuda_runtime.h>
#include <cuda_bf16.h>
#include <cstdint>

// ---------------- problem constants ----------------
#define CN 100000      // nodes
#define CE 1600000     // edges
#define CH 128         // hidden
#define CIN 32         // input feat
#define CG 64          // graphs
#define NB_SCAN ((CN + 1023) / 1024)

// ---------------- static device scratch ----------------
__device__ float g_h0[(size_t)CN * CH];
__device__ float g_h1[(size_t)CN * CH];
__device__ float g_d13[(size_t)CN * 2];
__device__ float g_inv[CN];
__device__ int   g_deg[CN];
__device__ int   g_cur[CN];
__device__ int   g_rowptr[CN];
__device__ int   g_bsums[NB_SCAN + 8];
__device__ int   g_csr[CE];
__device__ float g_gs[CG * 3];
__device__ int   g_gcnt[CG];
// split bf16 operand buffers
__device__ __nv_bfloat16 g_mh[(size_t)CN * CH], g_ml[(size_t)CN * CH];     // mean / a1
__device__ __nv_bfloat16 g_h0h[(size_t)CN * CH], g_h0l[(size_t)CN * CH];   // h0 split
__device__ __nv_bfloat16 g_h1h[(size_t)CN * CH], g_h1l[(size_t)CN * CH];   // h1 split
__device__ __nv_bfloat16 g_xh[(size_t)CN * CIN], g_xl[(size_t)CN * CIN];   // x split
// split transposed weights [N=128][Ktot] K-major
__device__ __nv_bfloat16 g_wt0h[128 * 64],  g_wt0l[128 * 64];
__device__ __nv_bfloat16 g_wt1h[128 * 256], g_wt1l[128 * 256];
__device__ __nv_bfloat16 g_wt2h[128 * 256], g_wt2l[128 * 256];
__device__ __nv_bfloat16 g_wtah[128 * 128], g_wtal[128 * 128];

// ---------------- helpers ----------------
__device__ __forceinline__ void mma_bf16(float* d, const uint32_t* a, const uint32_t* b) {
    asm volatile(
        "mma.sync.aligned.m16n8k16.row.col.f32.bf16.bf16.f32 "
        "{%0,%1,%2,%3}, {%4,%5,%6,%7}, {%8,%9}, {%0,%1,%2,%3};"
        : "+f"(d[0]), "+f"(d[1]), "+f"(d[2]), "+f"(d[3])
        : "r"(a[0]), "r"(a[1]), "r"(a[2]), "r"(a[3]), "r"(b[0]), "r"(b[1]));
}
__device__ __forceinline__ void bf16_split(float v, __nv_bfloat16& h, __nv_bfloat16& l) {
    h = __float2bfloat16_rn(v);
    l = __float2bfloat16_rn(v - __bfloat162float(h));
}
__device__ __forceinline__ uint32_t pack_bf(__nv_bfloat16 a, __nv_bfloat16 b) {
    __nv_bfloat162 t; t.x = a; t.y = b;
    return *(uint32_t*)&t;
}

// ---------------- CSR build kernels ----------------
__global__ void k_zero(int* deg, int* cur, float* gs, int* gcnt, int n) {
    int i = blockIdx.x * blockDim.x + threadIdx.x;
    if (i < n) { deg[i] = 0; cur[i] = 0; }
    if (i < CG * 3) gs[i] = 0.f;
    if (i < CG) gcnt[i] = 0;
}

__global__ void k_hist(const int* __restrict__ ei, int* deg, int E) {
    for (int e = blockIdx.x * blockDim.x + threadIdx.x; e < E; e += gridDim.x * blockDim.x)
        atomicAdd(&deg[ei[E + e]], 1);
}

__global__ void k_scan1(const int* __restrict__ deg, int* rowptr, int* bsums, int n) {
    __shared__ int sh[1024];
    int tid = threadIdx.x;
    int i = blockIdx.x * 1024 + tid;
    int v = (i < n) ? deg[i] : 0;
    sh[tid] = v;
    __syncthreads();
    for (int off = 1; off < 1024; off <<= 1) {
        int t = (tid >= off) ? sh[tid - off] : 0;
        __syncthreads();
        sh[tid] += t;
        __syncthreads();
    }
    if (i < n) rowptr[i] = sh[tid] - v;
    if (tid == 1023) bsums[blockIdx.x] = sh[1023];
}

__global__ void k_scan2(int* bsums, int nb) {
    __shared__ int sh[128];
    int t = threadIdx.x;
    int v = (t < nb) ? bsums[t] : 0;
    sh[t] = v;
    __syncthreads();
    for (int off = 1; off < 128; off <<= 1) {
        int u = (t >= off) ? sh[t - off] : 0;
        __syncthreads();
        sh[t] += u;
        __syncthreads();
    }
    if (t < nb) bsums[t] = sh[t] - v;
}

__global__ void k_scan3(int* rowptr, const int* __restrict__ bsums,
                        const int* __restrict__ deg, float* inv, int n) {
    int i = blockIdx.x * blockDim.x + threadIdx.x;
    if (i < n) {
        rowptr[i] += bsums[i >> 10];
        int d = deg[i];
        inv[i] = 1.0f / (float)(d > 0 ? d : 1);
    }
}

__global__ void k_fill(const int* __restrict__ ei, const int* __restrict__ rowptr,
                       int* cur, int* csr, int E) {
    for (int e = blockIdx.x * blockDim.x + threadIdx.x; e < E; e += gridDim.x * blockDim.x) {
        int s = ei[e];
        int d = ei[E + e];
        int pos = rowptr[d] + atomicAdd(&cur[d], 1);
        csr[pos] = s;
    }
}

// ---------------- weight transpose + split prep ----------------
__global__ void k_prep(const float* Wl0, const float* Wr0, const float* Wl1, const float* Wr1,
                       const float* Wl2, const float* Wr2, const float* Wa2,
                       __nv_bfloat16* w0h, __nv_bfloat16* w0l,
                       __nv_bfloat16* w1h, __nv_bfloat16* w1l,
                       __nv_bfloat16* w2h, __nv_bfloat16* w2l,
                       __nv_bfloat16* wah, __nv_bfloat16* wal) {
    int i = blockIdx.x * blockDim.x + threadIdx.x;
    float v; __nv_bfloat16 h, l;
    if (i < 8192) {                      // w0: [128][64]
        int n = i >> 6, k = i & 63;
        v = (k < 32) ? Wl0[k * 128 + n] : Wr0[(k - 32) * 128 + n];
        bf16_split(v, h, l); w0h[i] = h; w0l[i] = l;
    }
    int j = i - 8192;
    if (j >= 0 && j < 32768) {           // w1: [128][256]
        int n = j >> 8, k = j & 255;
        v = (k < 128) ? Wl1[k * 128 + n] : Wr1[(k - 128) * 128 + n];
        bf16_split(v, h, l); w1h[j] = h; w1l[j] = l;
    }
    int lq = i - 40960;
    if (lq >= 0 && lq < 32768) {         // w2
        int n = lq >> 8, k = lq & 255;
        v = (k < 128) ? Wl2[k * 128 + n] : Wr2[(k - 128) * 128 + n];
        bf16_split(v, h, l); w2h[lq] = h; w2l[lq] = l;
    }
    int m = i - 73728;
    if (m >= 0 && m < 16384) {           // wa: [128][128]
        int n = m >> 7, k = m & 127;
        v = Wa2[k * 128 + n];
        bf16_split(v, h, l); wah[m] = h; wal[m] = l;
    }
}

__global__ void k_splitx(const float* __restrict__ x, __nv_bfloat16* xh, __nv_bfloat16* xl, int n) {
    int i = blockIdx.x * blockDim.x + threadIdx.x;
    if (i < n) {
        __nv_bfloat16 h, l;
        bf16_split(x[i], h, l);
        xh[i] = h; xl[i] = l;
    }
}

// ---------------- aggregation (emit split bf16 mean) ----------------
__global__ void k_agg128(const float* __restrict__ h, const int* __restrict__ rowptr,
                         const int* __restrict__ deg, const float* __restrict__ inv,
                         const int* __restrict__ csr,
                         __nv_bfloat16* __restrict__ mh, __nv_bfloat16* __restrict__ ml, int N) {
    int w = (blockIdx.x * blockDim.x + threadIdx.x) >> 5;
    int lane = threadIdx.x & 31;
    if (w >= N) return;
    int start = rowptr[w];
    int d = deg[w];
    float4 acc = make_float4(0.f, 0.f, 0.f, 0.f);
    int i = 0;
    for (; i + 4 <= d; i += 4) {
        int s0 = __ldg(&csr[start + i]);
        int s1 = __ldg(&csr[start + i + 1]);
        int s2 = __ldg(&csr[start + i + 2]);
        int s3 = __ldg(&csr[start + i + 3]);
        float4 v0 = __ldg((const float4*)(h + (size_t)s0 * 128) + lane);
        float4 v1 = __ldg((const float4*)(h + (size_t)s1 * 128) + lane);
        float4 v2 = __ldg((const float4*)(h + (size_t)s2 * 128) + lane);
        float4 v3 = __ldg((const float4*)(h + (size_t)s3 * 128) + lane);
        acc.x += v0.x + v1.x + v2.x + v3.x;
        acc.y += v0.y + v1.y + v2.y + v3.y;
        acc.z += v0.z + v1.z + v2.z + v3.z;
        acc.w += v0.w + v1.w + v2.w + v3.w;
    }
    for (; i < d; i++) {
        int s = __ldg(&csr[start + i]);
        float4 v = __ldg((const float4*)(h + (size_t)s * 128) + lane);
        acc.x += v.x; acc.y += v.y; acc.z += v.z; acc.w += v.w;
    }
    float iv = inv[w];
    acc.x *= iv; acc.y *= iv; acc.z *= iv; acc.w *= iv;
    __nv_bfloat16 h0, l0, h1, l1, h2, l2, h3, l3;
    bf16_split(acc.x, h0, l0); bf16_split(acc.y, h1, l1);
    bf16_split(acc.z, h2, l2); bf16_split(acc.w, h3, l3);
    uint2 vh = make_uint2(pack_bf(h0, h1), pack_bf(h2, h3));
    uint2 vl = make_uint2(pack_bf(l0, l1), pack_bf(l2, l3));
    ((uint2*)(mh + (size_t)w * 128))[lane] = vh;
    ((uint2*)(ml + (size_t)w * 128))[lane] = vl;
}

__global__ void k_agg32(const float* __restrict__ h, const int* __restrict__ rowptr,
                        const int* __restrict__ deg, const float* __restrict__ inv,
                        const int* __restrict__ csr,
                        __nv_bfloat16* __restrict__ mh, __nv_bfloat16* __restrict__ ml, int N) {
    int w = (blockIdx.x * blockDim.x + threadIdx.x) >> 5;
    int lane = threadIdx.x & 31;
    if (w >= N) return;
    int start = rowptr[w];
    int d = deg[w];
    float acc = 0.f;
    int i = 0;
    for (; i + 4 <= d; i += 4) {
        int s0 = __ldg(&csr[start + i]);
        int s1 = __ldg(&csr[start + i + 1]);
        int s2 = __ldg(&csr[start + i + 2]);
        int s3 = __ldg(&csr[start + i + 3]);
        acc += __ldg(&h[(size_t)s0 * 32 + lane]) + __ldg(&h[(size_t)s1 * 32 + lane])
             + __ldg(&h[(size_t)s2 * 32 + lane]) + __ldg(&h[(size_t)s3 * 32 + lane]);
    }
    for (; i < d; i++) {
        int s = __ldg(&csr[start + i]);
        acc += __ldg(&h[(size_t)s * 32 + lane]);
    }
    acc *= inv[w];
    __nv_bfloat16 hh, ll;
    bf16_split(acc, hh, ll);
    mh[(size_t)w * 32 + lane] = hh;
    ml[(size_t)w * 32 + lane] = ll;
}

// ---------------- bf16-split tensor-core dual GEMM (pre-split operands) ----------------
// C = act( A1@W1 + (A2?@W2) + bias ); all operands already split hi/lo bf16.
#define APAD 20   // uint32 stride

__global__ __launch_bounds__(256)
void k_gemm_mma(const __nv_bfloat16* __restrict__ A1h, const __nv_bfloat16* __restrict__ A1l,
                const __nv_bfloat16* __restrict__ A2h, const __nv_bfloat16* __restrict__ A2l,
                const __nv_bfloat16* __restrict__ Wth, const __nv_bfloat16* __restrict__ Wtl,
                const float* __restrict__ bias, float* __restrict__ C,
                __nv_bfloat16* __restrict__ Ch, __nv_bfloat16* __restrict__ Cl,
                int M, int Kper, int relu) {
    __shared__ uint32_t sAh[128 * APAD], sAl[128 * APAD];
    __shared__ uint32_t sBh[128 * APAD], sBl[128 * APAD];

    int tid = threadIdx.x;
    int lane = tid & 31;
    int w = tid >> 5;
    int wm = (w >> 2) * 64;
    int wn = (w & 3) * 32;
    int m0 = blockIdx.x * 128;
    int r = lane >> 2, cc = lane & 3;

    float acc[4][4][4];
#pragma unroll
    for (int a = 0; a < 4; a++)
#pragma unroll
        for (int b = 0; b < 4; b++)
#pragma unroll
            for (int q = 0; q < 4; q++) acc[a][b][q] = 0.f;

    const int nA = Kper >> 5;
    const int nch = (A2h != nullptr) ? 2 * nA : nA;
    const int Ktot = nch << 5;

    for (int ch = 0; ch < nch; ch++) {
        const __nv_bfloat16* srcH = (ch < nA) ? A1h : A2h;
        const __nv_bfloat16* srcL = (ch < nA) ? A1l : A2l;
        int coff = ((ch < nA) ? ch : ch - nA) << 5;

        // A tile: 128 rows x 32 k, uint2 = 4 bf16 copies
#pragma unroll
        for (int q = 0; q < 4; q++) {
            int lin = tid + (q << 8);           // 0..1023
            int row = lin >> 3;
            int g = lin & 7;                     // 8 x uint2 per row
            int gm = m0 + row;
            uint2 vh = make_uint2(0u, 0u), vl = make_uint2(0u, 0u);
            if (gm < M) {
                vh = ((const uint2*)(srcH + (size_t)gm * Kper + coff))[g];
                vl = ((const uint2*)(srcL + (size_t)gm * Kper + coff))[g];
            }
            *(uint2*)&sAh[row * APAD + g * 2] = vh;
            *(uint2*)&sAl[row * APAD + g * 2] = vl;
        }
        // B tile: 128 n-rows x 32 k
#pragma unroll
        for (int q = 0; q < 4; q++) {
            int lin = tid + (q << 8);
            int row = lin >> 3;
            int g = lin & 7;
            uint2 vh = ((const uint2*)(Wth + (size_t)row * Ktot + (ch << 5)))[g];
            uint2 vl = ((const uint2*)(Wtl + (size_t)row * Ktot + (ch << 5)))[g];
            *(uint2*)&sBh[row * APAD + g * 2] = vh;
            *(uint2*)&sBl[row * APAD + g * 2] = vl;
        }
        __syncthreads();

#pragma unroll
        for (int ks = 0; ks < 2; ks++) {
            int kb = ks * 8;
            uint32_t ah[4][4], bh[4][2];
#pragma unroll
            for (int mt = 0; mt < 4; mt++) {
                int row = wm + mt * 16;
                ah[mt][0] = sAh[(row + r) * APAD + kb + cc];
                ah[mt][1] = sAh[(row + r + 8) * APAD + kb + cc];
                ah[mt][2] = sAh[(row + r) * APAD + kb + cc + 4];
                ah[mt][3] = sAh[(row + r + 8) * APAD + kb + cc + 4];
            }
#pragma unroll
            for (int nt = 0; nt < 4; nt++) {
                int col = wn + nt * 8;
                bh[nt][0] = sBh[(col + r) * APAD + kb + cc];
                bh[nt][1] = sBh[(col + r) * APAD + kb + cc + 4];
            }
#pragma unroll
            for (int mt = 0; mt < 4; mt++)
#pragma unroll
                for (int nt = 0; nt < 4; nt++)
                    mma_bf16(acc[mt][nt], ah[mt], bh[nt]);
            {
                uint32_t al[4][4];
#pragma unroll
                for (int mt = 0; mt < 4; mt++) {
                    int row = wm + mt * 16;
                    al[mt][0] = sAl[(row + r) * APAD + kb + cc];
                    al[mt][1] = sAl[(row + r + 8) * APAD + kb + cc];
                    al[mt][2] = sAl[(row + r) * APAD + kb + cc + 4];
                    al[mt][3] = sAl[(row + r + 8) * APAD + kb + cc + 4];
                }
#pragma unroll
                for (int mt = 0; mt < 4; mt++)
#pragma unroll
                    for (int nt = 0; nt < 4; nt++)
                        mma_bf16(acc[mt][nt], al[mt], bh[nt]);
            }
            {
                uint32_t bl[4][2];
#pragma unroll
                for (int nt = 0; nt < 4; nt++) {
                    int col = wn + nt * 8;
                    bl[nt][0] = sBl[(col + r) * APAD + kb + cc];
                    bl[nt][1] = sBl[(col + r) * APAD + kb + cc + 4];
                }
#pragma unroll
                for (int mt = 0; mt < 4; mt++)
#pragma unroll
                    for (int nt = 0; nt < 4; nt++)
                        mma_bf16(acc[mt][nt], ah[mt], bl[nt]);
            }
        }
        __syncthreads();
    }

    // epilogue: fp32 store + optional split bf16 store
#pragma unroll
    for (int mt = 0; mt < 4; mt++) {
#pragma unroll
        for (int nt = 0; nt < 4; nt++) {
            int col = wn + nt * 8 + cc * 2;
            float b0 = __ldg(&bias[col]);
            float b1 = __ldg(&bias[col + 1]);
            int gm0 = m0 + wm + mt * 16 + r;
            int gm1 = gm0 + 8;
            float v0 = acc[mt][nt][0] + b0;
            float v1 = acc[mt][nt][1] + b1;
            float v2 = acc[mt][nt][2] + b0;
            float v3 = acc[mt][nt][3] + b1;
            if (relu) {
                v0 = fmaxf(v0, 0.f); v1 = fmaxf(v1, 0.f);
                v2 = fmaxf(v2, 0.f); v3 = fmaxf(v3, 0.f);
            }
            if (gm0 < M) {
                *(float2*)&C[(size_t)gm0 * 128 + col] = make_float2(v0, v1);
                if (Ch) {
                    __nv_bfloat16 h0, l0, h1, l1;
                    bf16_split(v0, h0, l0); bf16_split(v1, h1, l1);
                    *(uint32_t*)&Ch[(size_t)gm0 * 128 + col] = pack_bf(h0, h1);
                    *(uint32_t*)&Cl[(size_t)gm0 * 128 + col] = pack_bf(l0, l1);
                }
            }
            if (gm1 < M) {
                *(float2*)&C[(size_t)gm1 * 128 + col] = make_float2(v2, v3);
                if (Ch) {
                    __nv_bfloat16 h2, l2, h3, l3;
                    bf16_split(v2, h2, l2); bf16_split(v3, h3, l3);
                    *(uint32_t*)&Ch[(size_t)gm1 * 128 + col] = pack_bf(h2, h3);
                    *(uint32_t*)&Cl[(size_t)gm1 * 128 + col] = pack_bf(l2, l3);
                }
            }
        }
    }
}

// ---------------- heads ----------------
__global__ void k_final1(const float* __restrict__ h, const float* __restrict__ Wfc,
                         const float* __restrict__ bfc, const float* __restrict__ Wa1,
                         const float* __restrict__ ba1, float* __restrict__ d13,
                         __nv_bfloat16* __restrict__ a1h, __nv_bfloat16* __restrict__ a1l, int M) {
    int gw = (blockIdx.x * blockDim.x + threadIdx.x) >> 5;
    int lane = threadIdx.x & 31;
    if (gw >= M) return;
    const float* hr = h + (size_t)gw * 128;
    float s0 = 0.f, s2 = 0.f;
    for (int k = lane; k < 128; k += 32) {
        float hv = hr[k];
        s0 += hv * __ldg(&Wfc[k * 3 + 0]);
        s2 += hv * __ldg(&Wfc[k * 3 + 2]);
    }
#pragma unroll
    for (int o = 16; o; o >>= 1) {
        s0 += __shfl_xor_sync(0xffffffffu, s0, o);
        s2 += __shfl_xor_sync(0xffffffffu, s2, o);
    }
    float d1 = s0 + __ldg(&bfc[0]);
    float d3 = s2 + __ldg(&bfc[2]);
    if (lane == 0) { d13[gw * 2] = d1; d13[gw * 2 + 1] = d3; }
    for (int j = lane; j < 128; j += 32) {
        float v = d1 * __ldg(&Wa1[j]) + d3 * __ldg(&Wa1[128 + j]) + __ldg(&ba1[j]);
        v = fmaxf(v, 0.f);
        __nv_bfloat16 hh, ll;
        bf16_split(v, hh, ll);
        a1h[(size_t)gw * 128 + j] = hh;
        a1l[(size_t)gw * 128 + j] = ll;
    }
}

__global__ void k_final3(const float* __restrict__ a2, const float* __restrict__ d13,
                         const float* __restrict__ Wao, const float* __restrict__ bao,
                         const int* __restrict__ batch, float* gs, int* gcnt, int M) {
    int gw = (blockIdx.x * blockDim.x + threadIdx.x) >> 5;
    int lane = threadIdx.x & 31;
    if (gw >= M) return;
    const float* ar = a2 + (size_t)gw * 128;
    float s = 0.f;
    for (int k = lane; k < 128; k += 32) s += ar[k] * __ldg(&Wao[k]);
#pragma unroll
    for (int o = 16; o; o >>= 1) s += __shfl_xor_sync(0xffffffffu, s, o);
    if (lane == 0) {
        float aux = s + __ldg(&bao[0]);
        int b = batch[gw];
        atomicAdd(&gs[b * 3 + 0], d13[gw * 2]);
        atomicAdd(&gs[b * 3 + 1], aux);
        atomicAdd(&gs[b * 3 + 2], d13[gw * 2 + 1]);
        atomicAdd(&gcnt[b], 1);
    }
}

__global__ void k_final4(const float* __restrict__ gs, const int* __restrict__ gcnt,
                         float* __restrict__ out) {
    int i = threadIdx.x;
    if (i < CG * 3) {
        int g = i / 3;
        int c = gcnt[g];
        out[i] = gs[i] / (float)(c > 0 ? c : 1);
    }
}

// ---------------- host launch ----------------
extern "C" void kernel_launch(void* const* d_in, const int* in_sizes, int n_in,
                              void* d_out, int out_size) {
    const float* x     = (const float*)d_in[0];
    const int*   ei    = (const int*)d_in[1];
    const int*   batch = (const int*)d_in[2];
    const float* Wl0 = (const float*)d_in[3];
    const float* bl0 = (const float*)d_in[4];
    const float* Wr0 = (const float*)d_in[5];
    const float* Wl1 = (const float*)d_in[6];
    const float* bl1 = (const float*)d_in[7];
    const float* Wr1 = (const float*)d_in[8];
    const float* Wl2 = (const float*)d_in[9];
    const float* bl2 = (const float*)d_in[10];
    const float* Wr2 = (const float*)d_in[11];
    const float* Wfc = (const float*)d_in[12];
    const float* bfc = (const float*)d_in[13];
    const float* Wa1 = (const float*)d_in[14];
    const float* ba1 = (const float*)d_in[15];
    const float* Wa2 = (const float*)d_in[16];
    const float* ba2 = (const float*)d_in[17];
    const float* Wao = (const float*)d_in[18];
    const float* bao = (const float*)d_in[19];
    float* out = (float*)d_out;

    const int N = in_sizes[0] / CIN;
    const int E = in_sizes[1] / 2;

    float *h0, *h1, *d13, *inv, *gs;
    int *deg, *cur, *rowptr, *bsums, *csr, *gcnt;
    __nv_bfloat16 *mh, *ml, *h0h, *h0l, *h1h, *h1l, *xh, *xl;
    __nv_bfloat16 *w0h, *w0l, *w1h, *w1l, *w2h, *w2l, *wah, *wal;
    cudaGetSymbolAddress((void**)&h0,     g_h0);
    cudaGetSymbolAddress((void**)&h1,     g_h1);
    cudaGetSymbolAddress((void**)&d13,    g_d13);
    cudaGetSymbolAddress((void**)&inv,    g_inv);
    cudaGetSymbolAddress((void**)&deg,    g_deg);
    cudaGetSymbolAddress((void**)&cur,    g_cur);
    cudaGetSymbolAddress((void**)&rowptr, g_rowptr);
    cudaGetSymbolAddress((void**)&bsums,  g_bsums);
    cudaGetSymbolAddress((void**)&csr,    g_csr);
    cudaGetSymbolAddress((void**)&gs,     g_gs);
    cudaGetSymbolAddress((void**)&gcnt,   g_gcnt);
    cudaGetSymbolAddress((void**)&mh,     g_mh);
    cudaGetSymbolAddress((void**)&ml,     g_ml);
    cudaGetSymbolAddress((void**)&h0h,    g_h0h);
    cudaGetSymbolAddress((void**)&h0l,    g_h0l);
    cudaGetSymbolAddress((void**)&h1h,    g_h1h);
    cudaGetSymbolAddress((void**)&h1l,    g_h1l);
    cudaGetSymbolAddress((void**)&xh,     g_xh);
    cudaGetSymbolAddress((void**)&xl,     g_xl);
    cudaGetSymbolAddress((void**)&w0h,    g_wt0h);
    cudaGetSymbolAddress((void**)&w0l,    g_wt0l);
    cudaGetSymbolAddress((void**)&w1h,    g_wt1h);
    cudaGetSymbolAddress((void**)&w1l,    g_wt1l);
    cudaGetSymbolAddress((void**)&w2h,    g_wt2h);
    cudaGetSymbolAddress((void**)&w2l,    g_wt2l);
    cudaGetSymbolAddress((void**)&wah,    g_wtah);
    cudaGetSymbolAddress((void**)&wal,    g_wtal);

    const int nbScan = (N + 1023) / 1024;
    const int gemmBlocks = (N + 127) / 128;
    const int warpNodeBlocks = (N * 32 + 255) / 256;

    // ---- CSR build + prep ----
    k_zero<<<(N + 255) / 256, 256>>>(deg, cur, gs, gcnt, N);
    k_hist<<<4096, 256>>>(ei, deg, E);
    k_prep<<<352, 256>>>(Wl0, Wr0, Wl1, Wr1, Wl2, Wr2, Wa2,
                         w0h, w0l, w1h, w1l, w2h, w2l, wah, wal);
    k_splitx<<<(N * CIN + 255) / 256, 256>>>(x, xh, xl, N * CIN);
    k_scan1<<<nbScan, 1024>>>(deg, rowptr, bsums, N);
    k_scan2<<<1, 128>>>(bsums, nbScan);
    k_scan3<<<(N + 255) / 256, 256>>>(rowptr, bsums, deg, inv, N);
    k_fill<<<4096, 256>>>(ei, rowptr, cur, csr, E);

    // ---- layer 0 (Kper=32) ----
    k_agg32<<<warpNodeBlocks, 256>>>(x, rowptr, deg, inv, csr, mh, ml, N);
    k_gemm_mma<<<gemmBlocks, 256>>>(mh, ml, xh, xl, w0h, w0l, bl0, h0, h0h, h0l, N, CIN, 1);

    // ---- layer 1 (Kper=128) ----
    k_agg128<<<warpNodeBlocks, 256>>>(h0, rowptr, deg, inv, csr, mh, ml, N);
    k_gemm_mma<<<gemmBlocks, 256>>>(mh, ml, h0h, h0l, w1h, w1l, bl1, h1, h1h, h1l, N, CH, 1);

    // ---- layer 2 (Kper=128) ----
    k_agg128<<<warpNodeBlocks, 256>>>(h1, rowptr, deg, inv, csr, mh, ml, N);
    k_gemm_mma<<<gemmBlocks, 256>>>(mh, ml, h1h, h1l, w2h, w2l, bl2, h0, nullptr, nullptr, N, CH, 1);

    // ---- heads ----
    k_final1<<<warpNodeBlocks, 256>>>(h0, Wfc, bfc, Wa1, ba1, d13, mh, ml, N);
    k_gemm_mma<<<gemmBlocks, 256>>>(mh, ml, nullptr, nullptr, wah, wal, ba2, h1, nullptr, nullptr, N, CH, 1);
    k_final3<<<warpNodeBlocks, 256>>>(h1, d13, Wao, bao, batch, gs, gcnt, N);
    k_final4<<<1, 256>>>(gs, gcnt, out);
}